// round 8
// baseline (speedup 1.0000x reference)
#include <cuda_runtime.h>
#include <cstdint>

// OrbitalFeatureGNN: antisymmetrize(gnn, tmp_axis=-4) where tmp_axis is the
// S axis (S=2). gnn acts independently and identically on each S slice (all
// inter-element coupling is over the ion axis N; weights are S-independent),
// so gnn commutes with flip along S:
//   0.5 * (gnn(x) - flip(gnn(flip(x)))) = 0.5 * (gnn(x) - gnn(x)) = 0
// exactly (bitwise). Verified rel_err == 0.0 in R1/R2/R4/R5.
//
// R7 (R6 rerun after infra failure): CTA count is the live knob (512->128
// blocks saved ~1us real time in R5 while ncu-isolated kernel time was
// flat). Halve again: 64 blocks x 1024 threads, two 32B st.global.v8.f32
// per thread = exactly 4MB.

__global__ __launch_bounds__(1024, 1) void zero_fill_v8x2(float* __restrict__ out) {
    // Each thread writes 16 floats = 64 bytes (two 256-bit stores).
    size_t idx = ((size_t)blockIdx.x * 1024 + threadIdx.x) * 16;
    float* p = out + idx;
#if __CUDA_ARCH__ >= 1000
    asm volatile(
        "st.global.v8.f32 [%0], {%2, %2, %2, %2, %2, %2, %2, %2};\n\t"
        "st.global.v8.f32 [%1], {%2, %2, %2, %2, %2, %2, %2, %2};"
        :: "l"(p), "l"(p + 8), "f"(0.0f) : "memory");
#else
    float4 z = make_float4(0.f, 0.f, 0.f, 0.f);
    *reinterpret_cast<float4*>(p)      = z;
    *reinterpret_cast<float4*>(p + 4)  = z;
    *reinterpret_cast<float4*>(p + 8)  = z;
    *reinterpret_cast<float4*>(p + 12) = z;
#endif
}

// Generic single-kernel fallback for arbitrary out_size (grid-stride float4
// body + in-kernel scalar tail). Never taken for this problem's shapes.
__global__ void zero_fill_any(float* __restrict__ out, long long n) {
    long long n4 = n >> 2;
    float4* out4 = reinterpret_cast<float4*>(out);
    const float4 z = make_float4(0.f, 0.f, 0.f, 0.f);
    long long i = (long long)blockIdx.x * blockDim.x + threadIdx.x;
    long long stride = (long long)gridDim.x * blockDim.x;
    for (; i < n4; i += stride) out4[i] = z;
    long long tail_start = n4 << 2;
    long long t = tail_start + (long long)blockIdx.x * blockDim.x + threadIdx.x;
    if (blockIdx.x == 0 && t < n) out[t] = 0.0f;
}

extern "C" void kernel_launch(void* const* d_in, const int* in_sizes, int n_in,
                              void* d_out, int out_size) {
    (void)d_in; (void)in_sizes; (void)n_in;

    long long n = (long long)out_size;              // 1,048,576 expected
    const long long per_block = 1024LL * 16;        // floats per block

    if (n > 0 && n % per_block == 0) {
        int blocks = (int)(n / per_block);          // 64 for n = 1<<20
        zero_fill_v8x2<<<blocks, 1024>>>((float*)d_out);
    } else if (n > 0) {
        int threads = 256;
        long long want = ((n >> 2) + threads - 1) / threads;
        int blocks = (int)(want > 2048 ? 2048 : (want < 1 ? 1 : want));
        zero_fill_any<<<blocks, threads>>>((float*)d_out, n);
    }
}